// round 1
// baseline (speedup 1.0000x reference)
#include <cuda_runtime.h>
#include <cstddef>
#include <cfloat>

// Problem constants (fixed by the dataset)
constexpr int Bq  = 16;
constexpr int Tq  = 768;
constexpr int Fq  = 512;
constexpr int FFq = 2048;
constexpr int Hq  = 8;
constexpr int DHq = 64;
constexpr int BTq = Bq * Tq;          // 12288
#define NEGC (-1000000000.0f)

// ---------------------------------------------------------------------------
// Device scratch (module-load allocated; allowed)
// ---------------------------------------------------------------------------
__device__ __align__(256) float g_xl [BTq * Fq];
__device__ __align__(256) float g_q  [BTq * Fq];
__device__ __align__(256) float g_k  [BTq * Fq];
__device__ __align__(256) float g_v  [BTq * Fq];
__device__ __align__(256) float g_ao [BTq * Fq];
__device__ __align__(256) float g_o  [BTq * Fq];
__device__ __align__(256) float g_y  [BTq * Fq];
__device__ __align__(256) float g_y2 [BTq * Fq];
__device__ __align__(256) float g_lx [BTq * Fq];
__device__ __align__(256) float g_pre[BTq * Fq];
__device__ __align__(256) float g_pln[BTq * Fq];
__device__ __align__(256) float g_gy [BTq * Fq];
__device__ __align__(256) float g_gy2[BTq * Fq];
__device__ __align__(256) float g_S  [(size_t)Bq * Hq * Tq * Tq];   // 302 MB
__device__ __align__(256) float g_ff [BTq * FFq];                   // 100 MB
__device__ __align__(256) float g_ls [BTq];
__device__ __align__(256) float g_hh2[BTq];
__device__ __align__(256) float g_wise[BTq];
__device__ __align__(256) float g_thr[Bq];
__device__ __align__(256) int   g_wid[BTq];
__device__ __align__(256) int   g_nb [Bq];

// ---------------------------------------------------------------------------
// Masks: sort + threshold + boundary logic + scan. One block (1024 thr) per b.
// ---------------------------------------------------------------------------
__global__ __launch_bounds__(1024) void masks_k(
    const float* __restrict__ hs, const float* __restrict__ mask,
    int* __restrict__ wid, int* __restrict__ nb,
    float* __restrict__ thr, float* __restrict__ wise)
{
    __shared__ float s[1024];
    __shared__ float fred[1024];
    __shared__ int   ibuf[1024];
    __shared__ int   sbuf[1024];
    __shared__ float thr_sh;
    const int b = blockIdx.x, tid = threadIdx.x;

    float h = 0.f;
    if (tid < Tq) h = hs[b * Tq + tid];
    s[tid]    = (tid < Tq) ? h : 3.402823466e+38f;
    fred[tid] = (tid < Tq) ? (1.0f - mask[b * Tq + tid]) : 0.f;
    __syncthreads();

    // reduce mask1 = sum(1 - mask)
    for (int off = 512; off > 0; off >>= 1) {
        if (tid < off) fred[tid] += fred[tid + off];
        __syncthreads();
    }
    const float mask1 = fred[0];
    __syncthreads();

    // bitonic sort ascending over 1024 padded values
    for (int kk = 2; kk <= 1024; kk <<= 1) {
        for (int j = kk >> 1; j > 0; j >>= 1) {
            const int ixj = tid ^ j;
            if (ixj > tid) {
                const float a = s[tid], c = s[ixj];
                const bool up = ((tid & kk) == 0);
                if ((a > c) == up) { s[tid] = c; s[ixj] = a; }
            }
            __syncthreads();
        }
    }
    if (tid == 0) {
        int med = (int)(mask1 * 0.5f + (float)Tq - mask1);
        med = min(max(med, 0), Tq - 1);
        thr_sh = s[med];
        thr[b] = thr_sh;
    }
    __syncthreads();
    const float thv = thr_sh;

    const int x1 = (tid < Tq && h >= thv) ? 1 : 0;
    ibuf[tid] = x1;
    __syncthreads();

    int x3a = 0;
    if (tid < Tq) x3a = (tid < Tq - 1) ? ((ibuf[tid + 1] != x1) ? 1 : 0) : 1;
    sbuf[tid] = x3a;
    __syncthreads();

    int x3 = x3a;
    if (tid > 0 && x3a == 1 && sbuf[tid - 1] == 1) x3 = 0;
    if (tid == Tq - 1) x3 = 1;
    __syncthreads();

    sbuf[tid] = (tid < Tq) ? x3 : 0;
    __syncthreads();
    // inclusive Hillis-Steele scan
    for (int off = 1; off < 1024; off <<= 1) {
        const int add = (tid >= off) ? sbuf[tid - off] : 0;
        __syncthreads();
        sbuf[tid] += add;
        __syncthreads();
    }
    if (tid < Tq) {
        wid[b * Tq + tid]  = sbuf[tid] - x3;
        wise[b * Tq + tid] = x1 ? 1.0f : 0.85f;
    }
    if (tid == Tq - 1) nb[b] = sbuf[tid];
}

// ---------------------------------------------------------------------------
// LayerNorm over F=512; optional residual add. One 128-thread block per row.
// ---------------------------------------------------------------------------
__global__ __launch_bounds__(128) void ln_k(
    const float* __restrict__ a, const float* __restrict__ res,
    float* __restrict__ o)
{
    const int row = blockIdx.x, tid = threadIdx.x;
    float4 v = ((const float4*)(a + (size_t)row * Fq))[tid];
    if (res) {
        const float4 r = ((const float4*)(res + (size_t)row * Fq))[tid];
        v.x += r.x; v.y += r.y; v.z += r.z; v.w += r.w;
    }
    float s  = v.x + v.y + v.z + v.w;
    float sq = v.x*v.x + v.y*v.y + v.z*v.z + v.w*v.w;
    #pragma unroll
    for (int off = 16; off > 0; off >>= 1) {
        s  += __shfl_xor_sync(0xffffffffu, s,  off);
        sq += __shfl_xor_sync(0xffffffffu, sq, off);
    }
    __shared__ float shs[4], shq[4];
    if ((tid & 31) == 0) { shs[tid >> 5] = s; shq[tid >> 5] = sq; }
    __syncthreads();
    s  = shs[0] + shs[1] + shs[2] + shs[3];
    sq = shq[0] + shq[1] + shq[2] + shq[3];
    const float m    = s * (1.0f / Fq);
    const float var  = fmaxf(sq * (1.0f / Fq) - m * m, 0.f);
    const float rstd = rsqrtf(var + 1e-5f);
    float4 w;
    w.x = (v.x - m) * rstd; w.y = (v.y - m) * rstd;
    w.z = (v.z - m) * rstd; w.w = (v.w - m) * rstd;
    ((float4*)(o + (size_t)row * Fq))[tid] = w;
}

// ---------------------------------------------------------------------------
// SGEMM: C[M,N] = A[M,K] @ B[K,N], 128x128x8 tiles, 8x8 per thread, fp32.
// M,N,K all divisible by tile sizes here.
// ---------------------------------------------------------------------------
template<bool RELU>
__global__ __launch_bounds__(256) void sgemm_k(
    int M, int N, int K,
    const float* __restrict__ A, const float* __restrict__ Bw,
    float* __restrict__ C)
{
    constexpr int BM = 128, BN = 128, BK = 8, TM = 8, TN = 8;
    __shared__ __align__(16) float As[BK][BM];
    __shared__ __align__(16) float Bs[BK][BN];
    const int tid  = threadIdx.x;
    const int tCol = tid & 15, tRow = tid >> 4;
    const float* Ab = A  + (size_t)blockIdx.y * BM * K;
    const float* Bb = Bw + (size_t)blockIdx.x * BN;
    float*       Cb = C  + (size_t)blockIdx.y * BM * N + (size_t)blockIdx.x * BN;
    const int aRow = tid >> 1, aCol = (tid & 1) << 2;
    const int bRow = tid >> 5, bCol = (tid & 31) << 2;
    float acc[TM][TN] = {};
    for (int k0 = 0; k0 < K; k0 += BK) {
        const float4 av = *(const float4*)(Ab + (size_t)aRow * K + k0 + aCol);
        As[aCol + 0][aRow] = av.x; As[aCol + 1][aRow] = av.y;
        As[aCol + 2][aRow] = av.z; As[aCol + 3][aRow] = av.w;
        *(float4*)(&Bs[bRow][bCol]) =
            *(const float4*)(Bb + (size_t)(k0 + bRow) * N + bCol);
        __syncthreads();
        #pragma unroll
        for (int kk = 0; kk < BK; kk++) {
            float rM[TM], rN[TN];
            #pragma unroll
            for (int i = 0; i < TM; i++) rM[i] = As[kk][tRow * TM + i];
            #pragma unroll
            for (int j = 0; j < TN; j++) rN[j] = Bs[kk][tCol * TN + j];
            #pragma unroll
            for (int i = 0; i < TM; i++)
                #pragma unroll
                for (int j = 0; j < TN; j++)
                    acc[i][j] += rM[i] * rN[j];
        }
        __syncthreads();
    }
    #pragma unroll
    for (int i = 0; i < TM; i++) {
        #pragma unroll
        for (int j = 0; j < TN; j += 4) {
            float4 v;
            v.x = acc[i][j];     v.y = acc[i][j + 1];
            v.z = acc[i][j + 2]; v.w = acc[i][j + 3];
            if (RELU) {
                v.x = fmaxf(v.x, 0.f); v.y = fmaxf(v.y, 0.f);
                v.z = fmaxf(v.z, 0.f); v.w = fmaxf(v.w, 0.f);
            }
            *(float4*)(Cb + (size_t)(tRow * TM + i) * N + tCol * TN + j) = v;
        }
    }
}

// ---------------------------------------------------------------------------
// Attention scores: S[bh,q,k] = (Q.Kt)*0.125 + mask.  64x64 tiles, K=64 resident.
// masktype 0: local (wid[q]!=wid[k]) ; masktype 1: global (k >= nb[b])
// ---------------------------------------------------------------------------
__global__ __launch_bounds__(256) void attn_qk(
    const float* __restrict__ q, const float* __restrict__ kin,
    float* __restrict__ S, const int* __restrict__ wid,
    const int* __restrict__ nb, int masktype)
{
    __shared__ __align__(16) float Qs[DHq][68];  // [d][m]
    __shared__ __align__(16) float Ks[DHq][68];  // [d][n]
    const int bh = blockIdx.z;
    const int b = bh >> 3, h = bh & 7;
    const int q0 = blockIdx.y * 64, k0 = blockIdx.x * 64;
    const int tid = threadIdx.x;
    for (int i = tid; i < 1024; i += 256) {
        const int r = i >> 4;
        const int c = (i & 15) << 2;
        const float4 qv = *(const float4*)(q   + ((size_t)(b * Tq + q0 + r)) * Fq + h * DHq + c);
        Qs[c + 0][r] = qv.x; Qs[c + 1][r] = qv.y; Qs[c + 2][r] = qv.z; Qs[c + 3][r] = qv.w;
        const float4 kv = *(const float4*)(kin + ((size_t)(b * Tq + k0 + r)) * Fq + h * DHq + c);
        Ks[c + 0][r] = kv.x; Ks[c + 1][r] = kv.y; Ks[c + 2][r] = kv.z; Ks[c + 3][r] = kv.w;
    }
    __syncthreads();
    const int tx = tid & 15, ty = tid >> 4;
    float acc[4][4] = {};
    #pragma unroll 8
    for (int d = 0; d < DHq; d++) {
        const float4 qv = *(const float4*)(&Qs[d][ty << 2]);
        const float4 kv = *(const float4*)(&Ks[d][tx << 2]);
        const float qa[4] = {qv.x, qv.y, qv.z, qv.w};
        const float ka[4] = {kv.x, kv.y, kv.z, kv.w};
        #pragma unroll
        for (int i = 0; i < 4; i++)
            #pragma unroll
            for (int j = 0; j < 4; j++)
                acc[i][j] += qa[i] * ka[j];
    }
    const float scale = 0.125f;
    float mk[4];
    int wq[4];
    if (masktype == 0) {
        int wk[4];
        #pragma unroll
        for (int i = 0; i < 4; i++) {
            wq[i] = wid[b * Tq + q0 + (ty << 2) + i];
            wk[i] = wid[b * Tq + k0 + (tx << 2) + i];
        }
        #pragma unroll
        for (int i = 0; i < 4; i++) {
            float4 ov;
            ov.x = acc[i][0] * scale + ((wq[i] != wk[0]) ? NEGC : 0.f);
            ov.y = acc[i][1] * scale + ((wq[i] != wk[1]) ? NEGC : 0.f);
            ov.z = acc[i][2] * scale + ((wq[i] != wk[2]) ? NEGC : 0.f);
            ov.w = acc[i][3] * scale + ((wq[i] != wk[3]) ? NEGC : 0.f);
            *(float4*)(S + ((size_t)bh * Tq + q0 + (ty << 2) + i) * Tq + k0 + (tx << 2)) = ov;
        }
    } else {
        const int nbv = nb[b];
        #pragma unroll
        for (int j = 0; j < 4; j++)
            mk[j] = ((k0 + (tx << 2) + j) >= nbv) ? NEGC : 0.f;
        #pragma unroll
        for (int i = 0; i < 4; i++) {
            float4 ov;
            ov.x = acc[i][0] * scale + mk[0];
            ov.y = acc[i][1] * scale + mk[1];
            ov.z = acc[i][2] * scale + mk[2];
            ov.w = acc[i][3] * scale + mk[3];
            *(float4*)(S + ((size_t)bh * Tq + q0 + (ty << 2) + i) * Tq + k0 + (tx << 2)) = ov;
        }
    }
}

// ---------------------------------------------------------------------------
// Row softmax over T=768. One 256-thread block per (b,h,q) row. In place.
// ---------------------------------------------------------------------------
__global__ __launch_bounds__(256) void softmax_rows(float* __restrict__ S)
{
    const size_t row = blockIdx.x;
    float* p = S + row * (size_t)Tq;
    const int tid = threadIdx.x;
    float v0 = p[tid], v1 = p[tid + 256], v2 = p[tid + 512];
    float mx = fmaxf(v0, fmaxf(v1, v2));
    #pragma unroll
    for (int off = 16; off > 0; off >>= 1)
        mx = fmaxf(mx, __shfl_xor_sync(0xffffffffu, mx, off));
    __shared__ float shm[8];
    if ((tid & 31) == 0) shm[tid >> 5] = mx;
    __syncthreads();
    mx = shm[0];
    #pragma unroll
    for (int i = 1; i < 8; i++) mx = fmaxf(mx, shm[i]);
    v0 = __expf(v0 - mx); v1 = __expf(v1 - mx); v2 = __expf(v2 - mx);
    float s = v0 + v1 + v2;
    #pragma unroll
    for (int off = 16; off > 0; off >>= 1)
        s += __shfl_xor_sync(0xffffffffu, s, off);
    __shared__ float shs[8];
    if ((tid & 31) == 0) shs[tid >> 5] = s;
    __syncthreads();
    s = shs[0] + shs[1] + shs[2] + shs[3] + shs[4] + shs[5] + shs[6] + shs[7];
    const float inv = 1.0f / s;
    p[tid] = v0 * inv; p[tid + 256] = v1 * inv; p[tid + 512] = v2 * inv;
}

// ---------------------------------------------------------------------------
// Column mean of A over (h, q): out[b,k] = mean_{h,q} A[b,h,q,k]
// ---------------------------------------------------------------------------
__global__ __launch_bounds__(256) void colmean(
    const float* __restrict__ S, float* __restrict__ outp)
{
    const int b = blockIdx.y;
    const int k = blockIdx.x * 256 + threadIdx.x;
    const float* p = S + (size_t)b * Hq * Tq * Tq + k;
    float a0 = 0, a1 = 0, a2 = 0, a3 = 0;
    #pragma unroll 4
    for (int r = 0; r < Hq * Tq; r += 4) {
        a0 += p[(size_t)(r + 0) * Tq];
        a1 += p[(size_t)(r + 1) * Tq];
        a2 += p[(size_t)(r + 2) * Tq];
        a3 += p[(size_t)(r + 3) * Tq];
    }
    outp[b * Tq + k] = (a0 + a1 + a2 + a3) * (1.0f / (Hq * Tq));
}

// ---------------------------------------------------------------------------
// AV: out[b,q,h,:] = A[bh] @ V_head. 64-row tiles, BK=16.
// ---------------------------------------------------------------------------
__global__ __launch_bounds__(256) void attn_av(
    const float* __restrict__ A, const float* __restrict__ v,
    float* __restrict__ o)
{
    __shared__ __align__(16) float As[16][68];  // [kk][m]
    __shared__ __align__(16) float Vs[16][68];  // [kk][d]
    const int bh = blockIdx.y;
    const int b = bh >> 3, h = bh & 7;
    const int q0 = blockIdx.x * 64;
    const int tid = threadIdx.x, tx = tid & 15, ty = tid >> 4;
    float acc[4][4] = {};
    for (int k0 = 0; k0 < Tq; k0 += 16) {
        {
            const int r = tid >> 2;
            const int c = (tid & 3) << 2;
            const float4 av = *(const float4*)(A + ((size_t)bh * Tq + q0 + r) * Tq + k0 + c);
            As[c + 0][r] = av.x; As[c + 1][r] = av.y;
            As[c + 2][r] = av.z; As[c + 3][r] = av.w;
        }
        {
            const int vr = tid >> 4;
            const int vc = (tid & 15) << 2;
            *(float4*)(&Vs[vr][vc]) =
                *(const float4*)(v + ((size_t)(b * Tq + k0 + vr)) * Fq + h * DHq + vc);
        }
        __syncthreads();
        #pragma unroll
        for (int kk = 0; kk < 16; kk++) {
            const float4 a4 = *(const float4*)(&As[kk][ty << 2]);
            const float4 v4 = *(const float4*)(&Vs[kk][tx << 2]);
            const float aa[4] = {a4.x, a4.y, a4.z, a4.w};
            const float vv[4] = {v4.x, v4.y, v4.z, v4.w};
            #pragma unroll
            for (int i = 0; i < 4; i++)
                #pragma unroll
                for (int j = 0; j < 4; j++)
                    acc[i][j] += aa[i] * vv[j];
        }
        __syncthreads();
    }
    #pragma unroll
    for (int i = 0; i < 4; i++) {
        float4 ov;
        ov.x = acc[i][0]; ov.y = acc[i][1]; ov.z = acc[i][2]; ov.w = acc[i][3];
        *(float4*)(o + ((size_t)(b * Tq + q0 + (ty << 2) + i)) * Fq + h * DHq + (tx << 2)) = ov;
    }
}

// ---------------------------------------------------------------------------
// Small elementwise helpers
// ---------------------------------------------------------------------------
__global__ void wise_mul(const float* __restrict__ y2, const float* __restrict__ wise,
                         float* __restrict__ lx)
{
    const int row = blockIdx.y;
    const int f = blockIdx.x * 256 + threadIdx.x;
    lx[(size_t)row * Fq + f] = y2[(size_t)row * Fq + f] * wise[row];
}

__global__ void zero_k(float* __restrict__ p, size_t n)
{
    const size_t i = (size_t)blockIdx.x * blockDim.x + threadIdx.x;
    if (i < n) p[i] = 0.f;
}

// pre[b, wid, f] = sum over contiguous window segment of lx*ls
__global__ __launch_bounds__(128) void agg_pre(
    const float* __restrict__ lx, const float* __restrict__ ls,
    const int* __restrict__ wid, float* __restrict__ pre)
{
    const int b = blockIdx.y;
    const int f = blockIdx.x * 128 + threadIdx.x;
    __shared__ int   sw[Tq];
    __shared__ float sl[Tq];
    for (int t = threadIdx.x; t < Tq; t += 128) {
        sw[t] = wid[b * Tq + t];
        sl[t] = ls[b * Tq + t];
    }
    __syncthreads();
    float acc = 0.f;
    for (int t = 0; t < Tq; t++) {
        acc += lx[((size_t)(b * Tq + t)) * Fq + f] * sl[t];
        const bool last = (t == Tq - 1) || (sw[t + 1] != sw[t]);
        if (last) {
            pre[((size_t)(b * Tq + sw[t])) * Fq + f] = acc;
            acc = 0.f;
        }
    }
}

__global__ void final_data(const float* __restrict__ lx, const float* __restrict__ gx,
                           const int* __restrict__ wid, float* __restrict__ out)
{
    const int row = blockIdx.y;
    const int f = blockIdx.x * 256 + threadIdx.x;
    const int b = row / Tq;
    const int w = wid[row];
    out[(size_t)row * Fq + f] =
        lx[(size_t)row * Fq + f] + gx[((size_t)(b * Tq + w)) * Fq + f];
}

__global__ __launch_bounds__(256) void final_attn(
    const float* __restrict__ ls, const float* __restrict__ hh2,
    const int* __restrict__ wid, const float* __restrict__ thr,
    float* __restrict__ out)
{
    const int b = blockIdx.x, tid = threadIdx.x;
    float v[3];
    #pragma unroll
    for (int i = 0; i < 3; i++) {
        const int t = tid + i * 256;
        v[i] = ls[b * Tq + t] * hh2[b * Tq + wid[b * Tq + t]];
    }
    float mx = fmaxf(v[0], fmaxf(v[1], v[2]));
    #pragma unroll
    for (int off = 16; off > 0; off >>= 1)
        mx = fmaxf(mx, __shfl_xor_sync(0xffffffffu, mx, off));
    __shared__ float shm[8];
    if ((tid & 31) == 0) shm[tid >> 5] = mx;
    __syncthreads();
    mx = shm[0];
    #pragma unroll
    for (int i = 1; i < 8; i++) mx = fmaxf(mx, shm[i]);
    float s = 0.f;
    #pragma unroll
    for (int i = 0; i < 3; i++) { v[i] = __expf(v[i] - mx); s += v[i]; }
    #pragma unroll
    for (int off = 16; off > 0; off >>= 1)
        s += __shfl_xor_sync(0xffffffffu, s, off);
    __shared__ float shs[8];
    if ((tid & 31) == 0) shs[tid >> 5] = s;
    __syncthreads();
    s = shs[0] + shs[1] + shs[2] + shs[3] + shs[4] + shs[5] + shs[6] + shs[7];
    const float inv = 1.0f / s;
    const size_t base = (size_t)BTq * Fq + Bq;  // after data + thresholds
    #pragma unroll
    for (int i = 0; i < 3; i++)
        out[base + (size_t)b * Tq + tid + i * 256] = v[i] * inv;
    if (tid == 0) out[(size_t)BTq * Fq + b] = thr[b];
}

// ---------------------------------------------------------------------------
// Host orchestration
// ---------------------------------------------------------------------------
extern "C" void kernel_launch(void* const* d_in, const int* in_sizes, int n_in,
                              void* d_out, int out_size)
{
    (void)in_sizes; (void)n_in;
    const float* x   = (const float*)d_in[0];
    const float* hs  = (const float*)d_in[1];
    const float* msk = (const float*)d_in[2];
    const float* W[12];
    for (int i = 0; i < 12; i++) W[i] = (const float*)d_in[3 + i];
    float* out = (float*)d_out;

    float *xl, *q, *k, *v, *ao, *o, *y, *y2, *lx, *pre, *pln, *gy, *gy2, *S, *ff;
    float *ls, *hh2, *wise, *thr;
    int *wid, *nb;
    cudaGetSymbolAddress((void**)&xl,  g_xl);
    cudaGetSymbolAddress((void**)&q,   g_q);
    cudaGetSymbolAddress((void**)&k,   g_k);
    cudaGetSymbolAddress((void**)&v,   g_v);
    cudaGetSymbolAddress((void**)&ao,  g_ao);
    cudaGetSymbolAddress((void**)&o,   g_o);
    cudaGetSymbolAddress((void**)&y,   g_y);
    cudaGetSymbolAddress((void**)&y2,  g_y2);
    cudaGetSymbolAddress((void**)&lx,  g_lx);
    cudaGetSymbolAddress((void**)&pre, g_pre);
    cudaGetSymbolAddress((void**)&pln, g_pln);
    cudaGetSymbolAddress((void**)&gy,  g_gy);
    cudaGetSymbolAddress((void**)&gy2, g_gy2);
    cudaGetSymbolAddress((void**)&S,   g_S);
    cudaGetSymbolAddress((void**)&ff,  g_ff);
    cudaGetSymbolAddress((void**)&ls,  g_ls);
    cudaGetSymbolAddress((void**)&hh2, g_hh2);
    cudaGetSymbolAddress((void**)&wise,g_wise);
    cudaGetSymbolAddress((void**)&thr, g_thr);
    cudaGetSymbolAddress((void**)&wid, g_wid);
    cudaGetSymbolAddress((void**)&nb,  g_nb);

    const dim3 gFF (Fq / 128, BTq / 128);     // (4, 96)
    const dim3 gFF1(FFq / 128, BTq / 128);    // (16, 96)
    const dim3 gQK (Tq / 64, Tq / 64, Bq * Hq);
    const dim3 gAV (Tq / 64, Bq * Hq);
    const dim3 gCM (Tq / 256, Bq);

    // masks + input LN
    masks_k<<<Bq, 1024>>>(hs, msk, wid, nb, thr, wise);
    ln_k<<<BTq, 128>>>(x, nullptr, xl);

    // ---------------- local transformer ----------------
    sgemm_k<false><<<gFF, 256>>>(BTq, Fq, Fq, xl, W[0], q);
    sgemm_k<false><<<gFF, 256>>>(BTq, Fq, Fq, xl, W[1], k);
    sgemm_k<false><<<gFF, 256>>>(BTq, Fq, Fq, xl, W[2], v);
    attn_qk<<<gQK, 256>>>(q, k, S, wid, nb, 0);
    softmax_rows<<<Bq * Hq * Tq, 256>>>(S);
    colmean<<<gCM, 256>>>(S, ls);
    attn_av<<<gAV, 256>>>(S, v, ao);
    sgemm_k<false><<<gFF, 256>>>(BTq, Fq, Fq, ao, W[3], o);
    ln_k<<<BTq, 128>>>(o, xl, y);
    sgemm_k<true ><<<gFF1, 256>>>(BTq, FFq, Fq, y, W[4], ff);
    sgemm_k<false><<<gFF, 256>>>(BTq, Fq, FFq, ff, W[5], o);
    ln_k<<<BTq, 128>>>(o, y, y2);
    wise_mul<<<dim3(Fq / 256, BTq), 256>>>(y2, wise, lx);

    // ---------------- window aggregation ----------------
    zero_k<<<(BTq * Fq + 1023) / 1024, 1024>>>(pre, (size_t)BTq * Fq);
    agg_pre<<<dim3(Fq / 128, Bq), 128>>>(lx, ls, wid, pre);
    ln_k<<<BTq, 128>>>(pre, nullptr, pln);

    // ---------------- global transformer ----------------
    sgemm_k<false><<<gFF, 256>>>(BTq, Fq, Fq, pln, W[6], q);
    sgemm_k<false><<<gFF, 256>>>(BTq, Fq, Fq, pln, W[7], k);
    sgemm_k<false><<<gFF, 256>>>(BTq, Fq, Fq, pln, W[8], v);
    attn_qk<<<gQK, 256>>>(q, k, S, wid, nb, 1);
    softmax_rows<<<Bq * Hq * Tq, 256>>>(S);
    colmean<<<gCM, 256>>>(S, hh2);
    attn_av<<<gAV, 256>>>(S, v, ao);
    sgemm_k<false><<<gFF, 256>>>(BTq, Fq, Fq, ao, W[9], o);
    ln_k<<<BTq, 128>>>(o, pln, gy);
    sgemm_k<true ><<<gFF1, 256>>>(BTq, FFq, Fq, gy, W[10], ff);
    sgemm_k<false><<<gFF, 256>>>(BTq, Fq, FFq, ff, W[11], o);
    ln_k<<<BTq, 128>>>(o, gy, gy2);

    // ---------------- outputs ----------------
    final_data<<<dim3(Fq / 256, BTq), 256>>>(lx, gy2, wid, out);
    if (out_size >= BTq * Fq + Bq + BTq)
        final_attn<<<Bq, 256>>>(ls, hh2, wid, thr, out);
}

// round 3
// speedup vs baseline: 2.0723x; 2.0723x over previous
#include <cuda_runtime.h>
#include <cstddef>
#include <cstdint>
#include <cfloat>

// Problem constants (fixed by the dataset)
constexpr int Bq  = 16;
constexpr int Tq  = 768;
constexpr int Fq  = 512;
constexpr int FFq = 2048;
constexpr int Hq  = 8;
constexpr int DHq = 64;
constexpr int BTq = Bq * Tq;          // 12288
#define NEGC (-1000000000.0f)

// ---------------------------------------------------------------------------
// Device scratch
// ---------------------------------------------------------------------------
__device__ __align__(256) float g_xl [BTq * Fq];
__device__ __align__(256) float g_q  [BTq * Fq];
__device__ __align__(256) float g_k  [BTq * Fq];
__device__ __align__(256) float g_v  [BTq * Fq];
__device__ __align__(256) float g_ao [BTq * Fq];
__device__ __align__(256) float g_o  [BTq * Fq];
__device__ __align__(256) float g_y  [BTq * Fq];
__device__ __align__(256) float g_y2 [BTq * Fq];
__device__ __align__(256) float g_lx [BTq * Fq];
__device__ __align__(256) float g_pre[BTq * Fq];
__device__ __align__(256) float g_pln[BTq * Fq];
__device__ __align__(256) float g_gy [BTq * Fq];
__device__ __align__(256) float g_gy2[BTq * Fq];
__device__ __align__(256) float g_S  [(size_t)Bq * Hq * Tq * Tq];   // 302 MB
__device__ __align__(256) float g_ff [BTq * FFq];                   // 100 MB
__device__ __align__(256) float g_ls [BTq];
__device__ __align__(256) float g_hh2[BTq];
__device__ __align__(256) float g_wise[BTq];
__device__ __align__(256) float g_thr[Bq];
__device__ __align__(256) int   g_wid[BTq];
__device__ __align__(256) int   g_nb [Bq];

// ---------------------------------------------------------------------------
// tf32 helpers
// ---------------------------------------------------------------------------
__device__ __forceinline__ uint32_t f2tf(float x) {
    uint32_t r;
    asm("cvt.rna.tf32.f32 %0, %1;" : "=r"(r) : "f"(x));
    return r;
}

__device__ __forceinline__ void mma_tf32(float* d, const uint32_t* a, const uint32_t* b) {
    asm volatile(
        "mma.sync.aligned.m16n8k8.row.col.f32.tf32.tf32.f32 "
        "{%0,%1,%2,%3}, {%4,%5,%6,%7}, {%8,%9}, {%0,%1,%2,%3};"
        : "+f"(d[0]), "+f"(d[1]), "+f"(d[2]), "+f"(d[3])
        : "r"(a[0]), "r"(a[1]), "r"(a[2]), "r"(a[3]), "r"(b[0]), "r"(b[1]));
}

// ---------------------------------------------------------------------------
// Masks: sort + threshold + boundary logic + scan. One block (1024 thr) per b.
// ---------------------------------------------------------------------------
__global__ __launch_bounds__(1024) void masks_k(
    const float* __restrict__ hs, const float* __restrict__ mask,
    int* __restrict__ wid, int* __restrict__ nb,
    float* __restrict__ thr, float* __restrict__ wise)
{
    __shared__ float s[1024];
    __shared__ float fred[1024];
    __shared__ int   ibuf[1024];
    __shared__ int   sbuf[1024];
    __shared__ float thr_sh;
    const int b = blockIdx.x, tid = threadIdx.x;

    float h = 0.f;
    if (tid < Tq) h = hs[b * Tq + tid];
    s[tid]    = (tid < Tq) ? h : 3.402823466e+38f;
    fred[tid] = (tid < Tq) ? (1.0f - mask[b * Tq + tid]) : 0.f;
    __syncthreads();

    for (int off = 512; off > 0; off >>= 1) {
        if (tid < off) fred[tid] += fred[tid + off];
        __syncthreads();
    }
    const float mask1 = fred[0];
    __syncthreads();

    for (int kk = 2; kk <= 1024; kk <<= 1) {
        for (int j = kk >> 1; j > 0; j >>= 1) {
            const int ixj = tid ^ j;
            if (ixj > tid) {
                const float a = s[tid], c = s[ixj];
                const bool up = ((tid & kk) == 0);
                if ((a > c) == up) { s[tid] = c; s[ixj] = a; }
            }
            __syncthreads();
        }
    }
    if (tid == 0) {
        int med = (int)(mask1 * 0.5f + (float)Tq - mask1);
        med = min(max(med, 0), Tq - 1);
        thr_sh = s[med];
        thr[b] = thr_sh;
    }
    __syncthreads();
    const float thv = thr_sh;

    const int x1 = (tid < Tq && h >= thv) ? 1 : 0;
    ibuf[tid] = x1;
    __syncthreads();

    int x3a = 0;
    if (tid < Tq) x3a = (tid < Tq - 1) ? ((ibuf[tid + 1] != x1) ? 1 : 0) : 1;
    sbuf[tid] = x3a;
    __syncthreads();

    int x3 = x3a;
    if (tid > 0 && x3a == 1 && sbuf[tid - 1] == 1) x3 = 0;
    if (tid == Tq - 1) x3 = 1;
    __syncthreads();

    sbuf[tid] = (tid < Tq) ? x3 : 0;
    __syncthreads();
    for (int off = 1; off < 1024; off <<= 1) {
        const int add = (tid >= off) ? sbuf[tid - off] : 0;
        __syncthreads();
        sbuf[tid] += add;
        __syncthreads();
    }
    if (tid < Tq) {
        wid[b * Tq + tid]  = sbuf[tid] - x3;
        wise[b * Tq + tid] = x1 ? 1.0f : 0.85f;
    }
    if (tid == Tq - 1) nb[b] = sbuf[tid];
}

// ---------------------------------------------------------------------------
// LayerNorm over F=512; optional residual add.
// ---------------------------------------------------------------------------
__global__ __launch_bounds__(128) void ln_k(
    const float* __restrict__ a, const float* __restrict__ res,
    float* __restrict__ o)
{
    const int row = blockIdx.x, tid = threadIdx.x;
    float4 v = ((const float4*)(a + (size_t)row * Fq))[tid];
    if (res) {
        const float4 r = ((const float4*)(res + (size_t)row * Fq))[tid];
        v.x += r.x; v.y += r.y; v.z += r.z; v.w += r.w;
    }
    float s  = v.x + v.y + v.z + v.w;
    float sq = v.x*v.x + v.y*v.y + v.z*v.z + v.w*v.w;
    #pragma unroll
    for (int off = 16; off > 0; off >>= 1) {
        s  += __shfl_xor_sync(0xffffffffu, s,  off);
        sq += __shfl_xor_sync(0xffffffffu, sq, off);
    }
    __shared__ float shs[4], shq[4];
    if ((tid & 31) == 0) { shs[tid >> 5] = s; shq[tid >> 5] = sq; }
    __syncthreads();
    s  = shs[0] + shs[1] + shs[2] + shs[3];
    sq = shq[0] + shq[1] + shq[2] + shq[3];
    const float m    = s * (1.0f / Fq);
    const float var  = fmaxf(sq * (1.0f / Fq) - m * m, 0.f);
    const float rstd = rsqrtf(var + 1e-5f);
    float4 w;
    w.x = (v.x - m) * rstd; w.y = (v.y - m) * rstd;
    w.z = (v.z - m) * rstd; w.w = (v.w - m) * rstd;
    ((float4*)(o + (size_t)row * Fq))[tid] = w;
}

// ---------------------------------------------------------------------------
// tf32 tensor-core GEMM: C[M,N] = A[M,K] @ B[K,N]. 128x128x16 tiles, 8 warps.
// ---------------------------------------------------------------------------
template<bool RELU>
__global__ __launch_bounds__(256) void gemm_tf32(
    int M, int N, int K,
    const float* __restrict__ A, const float* __restrict__ Bw,
    float* __restrict__ C)
{
    __shared__ uint32_t As[16][136];   // [k][m], stride 136 -> conflict-free frags
    __shared__ uint32_t Bs[16][136];   // [k][n]
    const int tid  = threadIdx.x;
    const int warp = tid >> 5, lane = tid & 31;
    const int gid = lane >> 2, tig = lane & 3;
    const int warpM = (warp >> 2) * 64, warpN = (warp & 3) * 32;
    const int m0blk = blockIdx.y * 128, n0blk = blockIdx.x * 128;

    const int aRow = tid >> 1, aC = (tid & 1) << 3;      // A: 128 rows x 16 k
    const int bRow = tid >> 4, bC = (tid & 15) << 3;     // B: 16 rows x 128 n
    const float* Ag = A  + (size_t)(m0blk + aRow) * K + aC;
    const float* Bg = Bw + (size_t)bRow * N + n0blk + bC;

    float4 pa0 = *(const float4*)(Ag);
    float4 pa1 = *(const float4*)(Ag + 4);
    float4 pb0 = *(const float4*)(Bg);
    float4 pb1 = *(const float4*)(Bg + 4);

    float acc[4][4][4] = {};

    for (int k0 = 0; k0 < K; k0 += 16) {
        __syncthreads();
        As[aC + 0][aRow] = f2tf(pa0.x); As[aC + 1][aRow] = f2tf(pa0.y);
        As[aC + 2][aRow] = f2tf(pa0.z); As[aC + 3][aRow] = f2tf(pa0.w);
        As[aC + 4][aRow] = f2tf(pa1.x); As[aC + 5][aRow] = f2tf(pa1.y);
        As[aC + 6][aRow] = f2tf(pa1.z); As[aC + 7][aRow] = f2tf(pa1.w);
        Bs[bRow][bC + 0] = f2tf(pb0.x); Bs[bRow][bC + 1] = f2tf(pb0.y);
        Bs[bRow][bC + 2] = f2tf(pb0.z); Bs[bRow][bC + 3] = f2tf(pb0.w);
        Bs[bRow][bC + 4] = f2tf(pb1.x); Bs[bRow][bC + 5] = f2tf(pb1.y);
        Bs[bRow][bC + 6] = f2tf(pb1.z); Bs[bRow][bC + 7] = f2tf(pb1.w);
        __syncthreads();
        if (k0 + 16 < K) {
            pa0 = *(const float4*)(Ag + k0 + 16);
            pa1 = *(const float4*)(Ag + k0 + 20);
            pb0 = *(const float4*)(Bg + (size_t)(k0 + 16) * N);
            pb1 = *(const float4*)(Bg + (size_t)(k0 + 16) * N + 4);
        }
        #pragma unroll
        for (int ks = 0; ks < 2; ks++) {
            const int kb = ks * 8;
            uint32_t af[4][4], bf[4][2];
            #pragma unroll
            for (int mf = 0; mf < 4; mf++) {
                const int m0 = warpM + mf * 16;
                af[mf][0] = As[kb + tig    ][m0 + gid];
                af[mf][1] = As[kb + tig    ][m0 + gid + 8];
                af[mf][2] = As[kb + tig + 4][m0 + gid];
                af[mf][3] = As[kb + tig + 4][m0 + gid + 8];
            }
            #pragma unroll
            for (int nf = 0; nf < 4; nf++) {
                const int n0 = warpN + nf * 8;
                bf[nf][0] = Bs[kb + tig    ][n0 + gid];
                bf[nf][1] = Bs[kb + tig + 4][n0 + gid];
            }
            #pragma unroll
            for (int mf = 0; mf < 4; mf++)
                #pragma unroll
                for (int nf = 0; nf < 4; nf++)
                    mma_tf32(acc[mf][nf], af[mf], bf[nf]);
        }
    }

    #pragma unroll
    for (int mf = 0; mf < 4; mf++) {
        const int r0 = m0blk + warpM + mf * 16 + gid;
        #pragma unroll
        for (int nf = 0; nf < 4; nf++) {
            const int c0 = n0blk + warpN + nf * 8 + tig * 2;
            float2 v0 = make_float2(acc[mf][nf][0], acc[mf][nf][1]);
            float2 v1 = make_float2(acc[mf][nf][2], acc[mf][nf][3]);
            if (RELU) {
                v0.x = fmaxf(v0.x, 0.f); v0.y = fmaxf(v0.y, 0.f);
                v1.x = fmaxf(v1.x, 0.f); v1.y = fmaxf(v1.y, 0.f);
            }
            *(float2*)(C + (size_t)r0 * N + c0)       = v0;
            *(float2*)(C + (size_t)(r0 + 8) * N + c0) = v1;
        }
    }
}

// ---------------------------------------------------------------------------
// QK^T with tf32 MMA: 128x128 tile per block, D=64 in 4 k-steps.
// masktype 0: local (wid[q]!=wid[k]); 1: global (k >= nb[b])
// ---------------------------------------------------------------------------
__global__ __launch_bounds__(256) void attn_qk_tf32(
    const float* __restrict__ q, const float* __restrict__ kin,
    float* __restrict__ S, const int* __restrict__ wid,
    const int* __restrict__ nb, int masktype)
{
    __shared__ uint32_t As[16][136];   // [d][qrow]
    __shared__ uint32_t Bs[16][136];   // [d][krow]
    __shared__ int sWq[128], sWk[128];
    const int bh = blockIdx.z;
    const int b = bh >> 3, h = bh & 7;
    const int q0 = blockIdx.y * 128, k0 = blockIdx.x * 128;
    const int tid = threadIdx.x;
    const int warp = tid >> 5, lane = tid & 31;
    const int gid = lane >> 2, tig = lane & 3;
    const int warpM = (warp >> 2) * 64, warpN = (warp & 3) * 32;

    if (masktype == 0 && tid < 128) {
        sWq[tid] = wid[b * Tq + q0 + tid];
        sWk[tid] = wid[b * Tq + k0 + tid];
    }

    const int row = tid >> 1, cc = (tid & 1) << 3;
    const float* qg = q   + (size_t)(b * Tq + q0 + row) * Fq + h * DHq + cc;
    const float* kg = kin + (size_t)(b * Tq + k0 + row) * Fq + h * DHq + cc;

    float acc[4][4][4] = {};
    for (int d0 = 0; d0 < DHq; d0 += 16) {
        const float4 qa = *(const float4*)(qg + d0);
        const float4 qb = *(const float4*)(qg + d0 + 4);
        const float4 ka = *(const float4*)(kg + d0);
        const float4 kb = *(const float4*)(kg + d0 + 4);
        __syncthreads();
        As[cc + 0][row] = f2tf(qa.x); As[cc + 1][row] = f2tf(qa.y);
        As[cc + 2][row] = f2tf(qa.z); As[cc + 3][row] = f2tf(qa.w);
        As[cc + 4][row] = f2tf(qb.x); As[cc + 5][row] = f2tf(qb.y);
        As[cc + 6][row] = f2tf(qb.z); As[cc + 7][row] = f2tf(qb.w);
        Bs[cc + 0][row] = f2tf(ka.x); Bs[cc + 1][row] = f2tf(ka.y);
        Bs[cc + 2][row] = f2tf(ka.z); Bs[cc + 3][row] = f2tf(ka.w);
        Bs[cc + 4][row] = f2tf(kb.x); Bs[cc + 5][row] = f2tf(kb.y);
        Bs[cc + 6][row] = f2tf(kb.z); Bs[cc + 7][row] = f2tf(kb.w);
        __syncthreads();
        #pragma unroll
        for (int ks = 0; ks < 2; ks++) {
            const int kbb = ks * 8;
            uint32_t af[4][4], bf[4][2];
            #pragma unroll
            for (int mf = 0; mf < 4; mf++) {
                const int m0 = warpM + mf * 16;
                af[mf][0] = As[kbb + tig    ][m0 + gid];
                af[mf][1] = As[kbb + tig    ][m0 + gid + 8];
                af[mf][2] = As[kbb + tig + 4][m0 + gid];
                af[mf][3] = As[kbb + tig + 4][m0 + gid + 8];
            }
            #pragma unroll
            for (int nf = 0; nf < 4; nf++) {
                const int n0 = warpN + nf * 8;
                bf[nf][0] = Bs[kbb + tig    ][n0 + gid];
                bf[nf][1] = Bs[kbb + tig + 4][n0 + gid];
            }
            #pragma unroll
            for (int mf = 0; mf < 4; mf++)
                #pragma unroll
                for (int nf = 0; nf < 4; nf++)
                    mma_tf32(acc[mf][nf], af[mf], bf[nf]);
        }
    }

    const float scale = 0.125f;
    const int nbv = (masktype == 1) ? nb[b] : 0;
    #pragma unroll
    for (int mf = 0; mf < 4; mf++) {
        const int rl0 = warpM + mf * 16 + gid;
        #pragma unroll
        for (int nf = 0; nf < 4; nf++) {
            const int cl = warpN + nf * 8 + tig * 2;
            float m00, m01, m10, m11;
            if (masktype == 0) {
                const int wk0 = sWk[cl], wk1 = sWk[cl + 1];
                const int wq0 = sWq[rl0], wq1 = sWq[rl0 + 8];
                m00 = (wq0 != wk0) ? NEGC : 0.f;
                m01 = (wq0 != wk1) ? NEGC : 0.f;
                m10 = (wq1 != wk0) ? NEGC : 0.f;
                m11 = (wq1 != wk1) ? NEGC : 0.f;
            } else {
                const float mk0 = ((k0 + cl)     >= nbv) ? NEGC : 0.f;
                const float mk1 = ((k0 + cl + 1) >= nbv) ? NEGC : 0.f;
                m00 = mk0; m01 = mk1; m10 = mk0; m11 = mk1;
            }
            float2 v0 = make_float2(acc[mf][nf][0] * scale + m00,
                                    acc[mf][nf][1] * scale + m01);
            float2 v1 = make_float2(acc[mf][nf][2] * scale + m10,
                                    acc[mf][nf][3] * scale + m11);
            *(float2*)(S + ((size_t)bh * Tq + q0 + rl0)     * Tq + k0 + cl) = v0;
            *(float2*)(S + ((size_t)bh * Tq + q0 + rl0 + 8) * Tq + k0 + cl) = v1;
        }
    }
}

// ---------------------------------------------------------------------------
// AV with tf32 MMA: out[b,q,h,:] = A[bh] @ V_head.  128x64 tile, K=768.
// ---------------------------------------------------------------------------
__global__ __launch_bounds__(256) void attn_av_tf32(
    const float* __restrict__ A, const float* __restrict__ v,
    float* __restrict__ o)
{
    __shared__ uint32_t As[16][136];   // [k][qrow]
    __shared__ uint32_t Bs[16][72];    // [k][d]
    const int bh = blockIdx.y;
    const int b = bh >> 3, h = bh & 7;
    const int q0 = blockIdx.x * 128;
    const int tid = threadIdx.x;
    const int warp = tid >> 5, lane = tid & 31;
    const int gid = lane >> 2, tig = lane & 3;
    const int warpM = (warp >> 1) * 32, warpN = (warp & 1) * 32;

    const int aRow = tid >> 1, aC = (tid & 1) << 3;
    const int bRow = tid >> 4, bC = (tid & 15) << 2;
    const float* Ag = A + ((size_t)bh * Tq + q0 + aRow) * Tq + aC;
    const float* Vg = v + (size_t)(b * Tq + bRow) * Fq + h * DHq + bC;

    float4 pa0 = *(const float4*)(Ag);
    float4 pa1 = *(const float4*)(Ag + 4);
    float4 pb0 = *(const float4*)(Vg);

    float acc[2][4][4] = {};
    for (int k0 = 0; k0 < Tq; k0 += 16) {
        __syncthreads();
        As[aC + 0][aRow] = f2tf(pa0.x); As[aC + 1][aRow] = f2tf(pa0.y);
        As[aC + 2][aRow] = f2tf(pa0.z); As[aC + 3][aRow] = f2tf(pa0.w);
        As[aC + 4][aRow] = f2tf(pa1.x); As[aC + 5][aRow] = f2tf(pa1.y);
        As[aC + 6][aRow] = f2tf(pa1.z); As[aC + 7][aRow] = f2tf(pa1.w);
        Bs[bRow][bC + 0] = f2tf(pb0.x); Bs[bRow][bC + 1] = f2tf(pb0.y);
        Bs[bRow][bC + 2] = f2tf(pb0.z); Bs[bRow][bC + 3] = f2tf(pb0.w);
        __syncthreads();
        if (k0 + 16 < Tq) {
            pa0 = *(const float4*)(Ag + k0 + 16);
            pa1 = *(const float4*)(Ag + k0 + 20);
            pb0 = *(const float4*)(Vg + (size_t)(k0 + 16) * Fq);
        }
        #pragma unroll
        for (int ks = 0; ks < 2; ks++) {
            const int kb = ks * 8;
            uint32_t af[2][4], bf[4][2];
            #pragma unroll
            for (int mf = 0; mf < 2; mf++) {
                const int m0 = warpM + mf * 16;
                af[mf][0] = As[kb + tig    ][m0 + gid];
                af[mf][1] = As[kb + tig    ][m0 + gid + 8];
                af[mf][2] = As[kb + tig + 4][m0 + gid];
                af[mf][3] = As[kb + tig + 4][m0 + gid + 8];
            }
            #pragma unroll
            for (int nf = 0; nf < 4; nf++) {
                const int n0 = warpN + nf * 8;
                bf[nf][0] = Bs[kb + tig    ][n0 + gid];
                bf[nf][1] = Bs[kb + tig + 4][n0 + gid];
            }
            #pragma unroll
            for (int mf = 0; mf < 2; mf++)
                #pragma unroll
                for (int nf = 0; nf < 4; nf++)
                    mma_tf32(acc[mf][nf], af[mf], bf[nf]);
        }
    }

    #pragma unroll
    for (int mf = 0; mf < 2; mf++) {
        const int r0 = q0 + warpM + mf * 16 + gid;
        #pragma unroll
        for (int nf = 0; nf < 4; nf++) {
            const int c0 = h * DHq + warpN + nf * 8 + tig * 2;
            *(float2*)(o + (size_t)(b * Tq + r0) * Fq + c0) =
                make_float2(acc[mf][nf][0], acc[mf][nf][1]);
            *(float2*)(o + (size_t)(b * Tq + r0 + 8) * Fq + c0) =
                make_float2(acc[mf][nf][2], acc[mf][nf][3]);
        }
    }
}

// ---------------------------------------------------------------------------
// Row softmax over T=768.
// ---------------------------------------------------------------------------
__global__ __launch_bounds__(256) void softmax_rows(float* __restrict__ S)
{
    const size_t row = blockIdx.x;
    float* p = S + row * (size_t)Tq;
    const int tid = threadIdx.x;
    float v0 = p[tid], v1 = p[tid + 256], v2 = p[tid + 512];
    float mx = fmaxf(v0, fmaxf(v1, v2));
    #pragma unroll
    for (int off = 16; off > 0; off >>= 1)
        mx = fmaxf(mx, __shfl_xor_sync(0xffffffffu, mx, off));
    __shared__ float shm[8];
    if ((tid & 31) == 0) shm[tid >> 5] = mx;
    __syncthreads();
    mx = shm[0];
    #pragma unroll
    for (int i = 1; i < 8; i++) mx = fmaxf(mx, shm[i]);
    v0 = __expf(v0 - mx); v1 = __expf(v1 - mx); v2 = __expf(v2 - mx);
    float s = v0 + v1 + v2;
    #pragma unroll
    for (int off = 16; off > 0; off >>= 1)
        s += __shfl_xor_sync(0xffffffffu, s, off);
    __shared__ float shs[8];
    if ((tid & 31) == 0) shs[tid >> 5] = s;
    __syncthreads();
    s = shs[0] + shs[1] + shs[2] + shs[3] + shs[4] + shs[5] + shs[6] + shs[7];
    const float inv = 1.0f / s;
    p[tid] = v0 * inv; p[tid + 256] = v1 * inv; p[tid + 512] = v2 * inv;
}

// ---------------------------------------------------------------------------
// Column mean of A over (h, q): out[b,k] = mean_{h,q} A[b,h,q,k]
// ---------------------------------------------------------------------------
__global__ __launch_bounds__(256) void colmean(
    const float* __restrict__ S, float* __restrict__ outp)
{
    const int b = blockIdx.y;
    const int k = blockIdx.x * 256 + threadIdx.x;
    const float* p = S + (size_t)b * Hq * Tq * Tq + k;
    float a0 = 0, a1 = 0, a2 = 0, a3 = 0;
    #pragma unroll 4
    for (int r = 0; r < Hq * Tq; r += 4) {
        a0 += p[(size_t)(r + 0) * Tq];
        a1 += p[(size_t)(r + 1) * Tq];
        a2 += p[(size_t)(r + 2) * Tq];
        a3 += p[(size_t)(r + 3) * Tq];
    }
    outp[b * Tq + k] = (a0 + a1 + a2 + a3) * (1.0f / (Hq * Tq));
}

// ---------------------------------------------------------------------------
// Small elementwise helpers
// ---------------------------------------------------------------------------
__global__ void wise_mul(const float* __restrict__ y2, const float* __restrict__ wise,
                         float* __restrict__ lx)
{
    const int row = blockIdx.y;
    const int f = blockIdx.x * 256 + threadIdx.x;
    lx[(size_t)row * Fq + f] = y2[(size_t)row * Fq + f] * wise[row];
}

__global__ void zero_k(float* __restrict__ p, size_t n)
{
    const size_t i = (size_t)blockIdx.x * blockDim.x + threadIdx.x;
    if (i < n) p[i] = 0.f;
}

__global__ __launch_bounds__(128) void agg_pre(
    const float* __restrict__ lx, const float* __restrict__ ls,
    const int* __restrict__ wid, float* __restrict__ pre)
{
    const int b = blockIdx.y;
    const int f = blockIdx.x * 128 + threadIdx.x;
    __shared__ int   sw[Tq];
    __shared__ float sl[Tq];
    for (int t = threadIdx.x; t < Tq; t += 128) {
        sw[t] = wid[b * Tq + t];
        sl[t] = ls[b * Tq + t];
    }
    __syncthreads();
    float acc = 0.f;
    for (int t = 0; t < Tq; t++) {
        acc += lx[((size_t)(b * Tq + t)) * Fq + f] * sl[t];
        const bool last = (t == Tq - 1) || (sw[t + 1] != sw[t]);
        if (last) {
            pre[((size_t)(b * Tq + sw[t])) * Fq + f] = acc;
            acc = 0.f;
        }
    }
}

__global__ void final_data(const float* __restrict__ lx, const float* __restrict__ gx,
                           const int* __restrict__ wid, float* __restrict__ out)
{
    const int row = blockIdx.y;
    const int f = blockIdx.x * 256 + threadIdx.x;
    const int b = row / Tq;
    const int w = wid[row];
    out[(size_t)row * Fq + f] =
        lx[(size_t)row * Fq + f] + gx[((size_t)(b * Tq + w)) * Fq + f];
}

__global__ __launch_bounds__(256) void final_attn(
    const float* __restrict__ ls, const float* __restrict__ hh2,
    const int* __restrict__ wid, const float* __restrict__ thr,
    float* __restrict__ out)
{
    const int b = blockIdx.x, tid = threadIdx.x;
    float v[3];
    #pragma unroll
    for (int i = 0; i < 3; i++) {
        const int t = tid + i * 256;
        v[i] = ls[b * Tq + t] * hh2[b * Tq + wid[b * Tq + t]];
    }
    float mx = fmaxf(v[0], fmaxf(v[1], v[2]));
    #pragma unroll
    for (int off = 16; off > 0; off >>= 1)
        mx = fmaxf(mx, __shfl_xor_sync(0xffffffffu, mx, off));
    __shared__ float shm[8];
    if ((tid & 31) == 0) shm[tid >> 5] = mx;
    __syncthreads();
    mx = shm[0];
    #pragma unroll
    for (int i = 1; i < 8; i++) mx = fmaxf(mx, shm[i]);
    float s = 0.f;
    #pragma unroll
    for (int i = 0; i < 3; i++) { v[i] = __expf(v[i] - mx); s += v[i]; }
    #pragma unroll
    for (int off = 16; off > 0; off >>= 1)
        s += __shfl_xor_sync(0xffffffffu, s, off);
    __shared__ float shs[8];
    if ((tid & 31) == 0) shs[tid >> 5] = s;
    __syncthreads();
    s = shs[0] + shs[1] + shs[2] + shs[3] + shs[4] + shs[5] + shs[6] + shs[7];
    const float inv = 1.0f / s;
    const size_t base = (size_t)BTq * Fq + Bq;
    #pragma unroll
    for (int i = 0; i < 3; i++)
        out[base + (size_t)b * Tq + tid + i * 256] = v[i] * inv;
    if (tid == 0) out[(size_t)BTq * Fq + b] = thr[b];
}

// ---------------------------------------------------------------------------
// Host orchestration
// ---------------------------------------------------------------------------
extern "C" void kernel_launch(void* const* d_in, const int* in_sizes, int n_in,
                              void* d_out, int out_size)
{
    (void)in_sizes; (void)n_in;
    const float* x   = (const float*)d_in[0];
    const float* hs  = (const float*)d_in[1];
    const float* msk = (const float*)d_in[2];
    const float* W[12];
    for (int i = 0; i < 12; i++) W[i] = (const float*)d_in[3 + i];
    float* out = (float*)d_out;

    float *xl, *q, *k, *v, *ao, *o, *y, *y2, *lx, *pre, *pln, *gy, *gy2, *S, *ff;
    float *ls, *hh2, *wise, *thr;
    int *wid, *nb;
    cudaGetSymbolAddress((void**)&xl,  g_xl);
    cudaGetSymbolAddress((void**)&q,   g_q);
    cudaGetSymbolAddress((void**)&k,   g_k);
    cudaGetSymbolAddress((void**)&v,   g_v);
    cudaGetSymbolAddress((void**)&ao,  g_ao);
    cudaGetSymbolAddress((void**)&o,   g_o);
    cudaGetSymbolAddress((void**)&y,   g_y);
    cudaGetSymbolAddress((void**)&y2,  g_y2);
    cudaGetSymbolAddress((void**)&lx,  g_lx);
    cudaGetSymbolAddress((void**)&pre, g_pre);
    cudaGetSymbolAddress((void**)&pln, g_pln);
    cudaGetSymbolAddress((void**)&gy,  g_gy);
    cudaGetSymbolAddress((void**)&gy2, g_gy2);
    cudaGetSymbolAddress((void**)&S,   g_S);
    cudaGetSymbolAddress((void**)&ff,  g_ff);
    cudaGetSymbolAddress((void**)&ls,  g_ls);
    cudaGetSymbolAddress((void**)&hh2, g_hh2);
    cudaGetSymbolAddress((void**)&wise,g_wise);
    cudaGetSymbolAddress((void**)&thr, g_thr);
    cudaGetSymbolAddress((void**)&wid, g_wid);
    cudaGetSymbolAddress((void**)&nb,  g_nb);

    const dim3 gFF (Fq / 128, BTq / 128);     // (4, 96)
    const dim3 gFF1(FFq / 128, BTq / 128);    // (16, 96)
    const dim3 gQK (Tq / 128, Tq / 128, Bq * Hq);
    const dim3 gAV (Tq / 128, Bq * Hq);
    const dim3 gCM (Tq / 256, Bq);

    masks_k<<<Bq, 1024>>>(hs, msk, wid, nb, thr, wise);
    ln_k<<<BTq, 128>>>(x, nullptr, xl);

    // ---------------- local transformer ----------------
    gemm_tf32<false><<<gFF, 256>>>(BTq, Fq, Fq, xl, W[0], q);
    gemm_tf32<false><<<gFF, 256>>>(BTq, Fq, Fq, xl, W[1], k);
    gemm_tf32<false><<<gFF, 256>>>(BTq, Fq, Fq, xl, W[2], v);
    attn_qk_tf32<<<gQK, 256>>>(q, k, S, wid, nb, 0);
    softmax_rows<<<Bq * Hq * Tq, 256>>>(S);
    colmean<<<gCM, 256>>>(S, ls);
    attn_av_tf32<<<gAV, 256>>>(S, v, ao);
    gemm_tf32<false><<<gFF, 256>>>(BTq, Fq, Fq, ao, W[3], o);
    ln_k<<<BTq, 128>>>(o, xl, y);
    gemm_tf32<true ><<<gFF1, 256>>>(BTq, FFq, Fq, y, W[4], ff);
    gemm_tf32<false><<<gFF, 256>>>(BTq, Fq, FFq, ff, W[5], o);
    ln_k<<<BTq, 128>>>(o, y, y2);
    wise_mul<<<dim3(Fq / 256, BTq), 256>>>(y2, wise, lx);

    // ---------------- window aggregation ----------------
    zero_k<<<(BTq * Fq + 1023) / 1024, 1024>>>(pre, (size_t)BTq * Fq);
    agg_pre<<<dim3(Fq / 128, Bq), 128>>>(lx, ls, wid, pre);
    ln_k<<<BTq, 128>>>(pre, nullptr, pln);

    // ---------------- global transformer ----------------
    gemm_tf32<false><<<gFF, 256>>>(BTq, Fq, Fq, pln, W[6], q);
    gemm_tf32<false><<<gFF, 256>>>(BTq, Fq, Fq, pln, W[7], k);
    gemm_tf32<false><<<gFF, 256>>>(BTq, Fq, Fq, pln, W[8], v);
    attn_qk_tf32<<<gQK, 256>>>(q, k, S, wid, nb, 1);
    softmax_rows<<<Bq * Hq * Tq, 256>>>(S);
    colmean<<<gCM, 256>>>(S, hh2);
    attn_av_tf32<<<gAV, 256>>>(S, v, ao);
    gemm_tf32<false><<<gFF, 256>>>(BTq, Fq, Fq, ao, W[9], o);
    ln_k<<<BTq, 128>>>(o, pln, gy);
    gemm_tf32<true ><<<gFF1, 256>>>(BTq, FFq, Fq, gy, W[10], ff);
    gemm_tf32<false><<<gFF, 256>>>(BTq, Fq, FFq, ff, W[11], o);
    ln_k<<<BTq, 128>>>(o, gy, gy2);

    // ---------------- outputs ----------------
    final_data<<<dim3(Fq / 256, BTq), 256>>>(lx, gy2, wid, out);
    if (out_size >= BTq * Fq + Bq + BTq)
        final_attn<<<Bq, 256>>>(ls, hh2, wid, thr, out);
}